// round 12
// baseline (speedup 1.0000x reference)
#include <cuda_runtime.h>
#include <cuda_bf16.h>

// CenterLoss collapses: the label mask keeps only distmat[b, labels[b]]; all
// other B*(C-1) entries are 0 -> clamped to CLAMP_MIN.
// loss = (sum_b clamp(||x_b - c_{lbl_b}||^2, MIN, MAX)) / B + (C-1)*CLAMP_MIN.
// Labels are INT32 (established R2..R5).
//
// R12 = R10 (best, 6.30us: init node + PDL rows + per-block RED) with the
// per-warp critical path halved: float4 loads (16 lanes/row -> 4 LDG/lane
// instead of 8) and 10 shuffles/warp instead of 20. R11 showed the envelope
// is mostly fixed cost at idle clocks; cycles on the path are the only lever.

#define BATCH 4096
#define NUM_CLASSES 100000
#define FEAT_DIM 64
#define CLAMP_MIN_F 1e-12f
#define CLAMP_MAX_F 1e12f

#define BLOCK_THREADS 256
#define WARPS_PER_BLOCK 8
#define ROWS_PER_WARP 4
#define ROWS_PER_BLOCK (WARPS_PER_BLOCK * ROWS_PER_WARP)   // 32
#define NUM_BLOCKS (BATCH / ROWS_PER_BLOCK)                // 128 -> single wave

__global__ void __launch_bounds__(32)
center_loss_init(float* __restrict__ out) {
    // (C-1) masked zeros per row -> CLAMP_MIN each; /B leaves (C-1)*MIN.
    if (threadIdx.x == 0)
        out[0] = (float)(NUM_CLASSES - 1) * CLAMP_MIN_F;
}

__global__ void __launch_bounds__(BLOCK_THREADS)
center_loss_rows(const float* __restrict__ x,
                 const float* __restrict__ centers,
                 const int* __restrict__ labels,
                 float* __restrict__ out) {
    const int warp = threadIdx.x >> 5;
    const int lane = threadIdx.x & 31;
    const int row0 = blockIdx.x * ROWS_PER_BLOCK + warp * ROWS_PER_WARP;

    // One broadcast LDG.128 for this warp's 4 labels (row0 % 4 == 0).
    const int4 lraw = *reinterpret_cast<const int4*>(labels + row0);
    // Crash guard (free): bad label -> wrong value, never a fault.
    int lb0 = (lraw.x < 0) ? 0 : (lraw.x >= NUM_CLASSES ? NUM_CLASSES - 1 : lraw.x);
    int lb1 = (lraw.y < 0) ? 0 : (lraw.y >= NUM_CLASSES ? NUM_CLASSES - 1 : lraw.y);
    int lb2 = (lraw.z < 0) ? 0 : (lraw.z >= NUM_CLASSES ? NUM_CLASSES - 1 : lraw.z);
    int lb3 = (lraw.w < 0) ? 0 : (lraw.w >= NUM_CLASSES ? NUM_CLASSES - 1 : lraw.w);

    // float4 layout: 16 lanes cover one 64-float row. Warp-wide load covers
    // 2 rows. Slot 0 -> rows row0+0 (lanes 0-15) / row0+1 (lanes 16-31);
    // slot 1 -> rows row0+2 / row0+3.
    const bool hi = (lane >= 16);
    const int col = lane & 15;
    const int rA = row0 + (hi ? 1 : 0);      // slot 0 row for this lane
    const int rB = row0 + 2 + (hi ? 1 : 0);  // slot 1 row for this lane
    const int lA = hi ? lb1 : lb0;
    const int lB = hi ? lb3 : lb2;

    // 4 independent 16B loads per lane; rows are 256B-aligned & coalesced.
    const float4 xa = reinterpret_cast<const float4*>(x + (size_t)rA * FEAT_DIM)[col];
    const float4 xb = reinterpret_cast<const float4*>(x + (size_t)rB * FEAT_DIM)[col];
    const float4 ca = reinterpret_cast<const float4*>(centers + (size_t)lA * FEAT_DIM)[col];
    const float4 cb = reinterpret_cast<const float4*>(centers + (size_t)lB * FEAT_DIM)[col];

    float d;
    float a0, a1;
    d = xa.x - ca.x; a0  = d * d;
    d = xa.y - ca.y; a0 += d * d;
    d = xa.z - ca.z; a0 += d * d;
    d = xa.w - ca.w; a0 += d * d;
    d = xb.x - cb.x; a1  = d * d;
    d = xb.y - cb.y; a1 += d * d;
    d = xb.z - cb.z; a1 += d * d;
    d = xb.w - cb.w; a1 += d * d;

    // Reduce within each 16-lane half (4 steps), both slots interleaved.
    #pragma unroll
    for (int o = 8; o > 0; o >>= 1) {
        a0 += __shfl_xor_sync(0xffffffffu, a0, o);
        a1 += __shfl_xor_sync(0xffffffffu, a1, o);
    }
    // Bring the upper half's row-sums down: on lane 0, b* = rows row0+1/row0+3.
    const float b0 = __shfl_xor_sync(0xffffffffu, a0, 16);
    const float b1 = __shfl_xor_sync(0xffffffffu, a1, 16);

    __shared__ float ws[WARPS_PER_BLOCK];
    if (lane == 0) {
        // clamp per ROW (clip-then-sum), fixed order rows 0,1,2,3.
        float s = fminf(fmaxf(a0, CLAMP_MIN_F), CLAMP_MAX_F);
        s      += fminf(fmaxf(b0, CLAMP_MIN_F), CLAMP_MAX_F);
        s      += fminf(fmaxf(a1, CLAMP_MIN_F), CLAMP_MAX_F);
        s      += fminf(fmaxf(b1, CLAMP_MIN_F), CLAMP_MAX_F);
        ws[warp] = s;
    }
    __syncthreads();

    if (threadIdx.x == 0) {
        float v = 0.0f;
        #pragma unroll
        for (int w = 0; w < WARPS_PER_BLOCK; w++) v += ws[w];
        // Ensure the init kernel's out[0]=mask_term is complete & visible.
        cudaGridDependencySynchronize();
        // No-return atomic add -> RED; 128 single-address REDs ~ 110 cycles.
        atomicAdd(out, v * (1.0f / (float)BATCH));
    }
}

extern "C" void kernel_launch(void* const* d_in, const int* in_sizes, int n_in,
                              void* d_out, int out_size) {
    const float* x       = (const float*)d_in[0];
    const float* centers = (const float*)d_in[1];
    const int*   labels  = (const int*)d_in[2];
    float* out = (float*)d_out;

    center_loss_init<<<1, 32>>>(out);

    // PDL: rows launches while init is in flight; the grid-dependency sync
    // inside rows (before the REDs) provides the ordering.
    cudaLaunchConfig_t cfg = {};
    cfg.gridDim  = dim3(NUM_BLOCKS, 1, 1);
    cfg.blockDim = dim3(BLOCK_THREADS, 1, 1);
    cfg.dynamicSmemBytes = 0;
    cfg.stream = 0;   // same (capture) stream as the launch above
    cudaLaunchAttribute attr[1];
    attr[0].id = cudaLaunchAttributeProgrammaticStreamSerialization;
    attr[0].val.programmaticStreamSerializationAllowed = 1;
    cfg.attrs = attr;
    cfg.numAttrs = 1;
    cudaLaunchKernelEx(&cfg, center_loss_rows, x, centers, labels, out);
}

// round 13
// speedup vs baseline: 1.0049x; 1.0049x over previous
#include <cuda_runtime.h>
#include <cuda_bf16.h>

// CenterLoss collapses: the label mask keeps only distmat[b, labels[b]]; all
// other B*(C-1) entries are 0 -> clamped to CLAMP_MIN.
// loss = (sum_b clamp(||x_b - c_{lbl_b}||^2, MIN, MAX)) / B + (C-1)*CLAMP_MIN.
// Labels are INT32 (established R2..R5).
//
// R13 = single graph node (R11 protocol: RED to g_acc + acq_rel counter,
// winner writes out and resets) carrying R12's slim math (float4 loads,
// 16 lanes/row, 10 shuffles/warp). Wall time is at the replay-overhead
// floor (R10-R12 spread 6.30-6.53us); minimize node count + path cycles.

#define BATCH 4096
#define NUM_CLASSES 100000
#define FEAT_DIM 64
#define CLAMP_MIN_F 1e-12f
#define CLAMP_MAX_F 1e12f

#define BLOCK_THREADS 256
#define WARPS_PER_BLOCK 8
#define ROWS_PER_WARP 4
#define ROWS_PER_BLOCK (WARPS_PER_BLOCK * ROWS_PER_WARP)   // 32
#define NUM_BLOCKS (BATCH / ROWS_PER_BLOCK)                // 128 -> single wave

__device__ float        g_acc = 0.0f;         // reset by winner each call
__device__ unsigned int g_arrive_count = 0;   // reset by winner each call

__global__ void __launch_bounds__(BLOCK_THREADS)
center_loss_fused(const float* __restrict__ x,
                  const float* __restrict__ centers,
                  const int* __restrict__ labels,
                  float* __restrict__ out) {
    const int warp = threadIdx.x >> 5;
    const int lane = threadIdx.x & 31;
    const int row0 = blockIdx.x * ROWS_PER_BLOCK + warp * ROWS_PER_WARP;

    // One broadcast LDG.128 for this warp's 4 labels (row0 % 4 == 0).
    const int4 lraw = *reinterpret_cast<const int4*>(labels + row0);
    // Crash guard (free): bad label -> wrong value, never a fault.
    const int lb0 = (lraw.x < 0) ? 0 : (lraw.x >= NUM_CLASSES ? NUM_CLASSES - 1 : lraw.x);
    const int lb1 = (lraw.y < 0) ? 0 : (lraw.y >= NUM_CLASSES ? NUM_CLASSES - 1 : lraw.y);
    const int lb2 = (lraw.z < 0) ? 0 : (lraw.z >= NUM_CLASSES ? NUM_CLASSES - 1 : lraw.z);
    const int lb3 = (lraw.w < 0) ? 0 : (lraw.w >= NUM_CLASSES ? NUM_CLASSES - 1 : lraw.w);

    // float4 layout: 16 lanes cover one 64-float row; warp-wide load = 2 rows.
    const bool hi = (lane >= 16);
    const int col = lane & 15;
    const int rA = row0 + (hi ? 1 : 0);       // slot 0: rows row0+0 / row0+1
    const int rB = row0 + 2 + (hi ? 1 : 0);   // slot 1: rows row0+2 / row0+3
    const int lA = hi ? lb1 : lb0;
    const int lB = hi ? lb3 : lb2;

    // 4 independent 16B loads per lane; rows are 256B-aligned & coalesced.
    const float4 xa = reinterpret_cast<const float4*>(x + (size_t)rA * FEAT_DIM)[col];
    const float4 xb = reinterpret_cast<const float4*>(x + (size_t)rB * FEAT_DIM)[col];
    const float4 ca = reinterpret_cast<const float4*>(centers + (size_t)lA * FEAT_DIM)[col];
    const float4 cb = reinterpret_cast<const float4*>(centers + (size_t)lB * FEAT_DIM)[col];

    float d;
    float a0, a1;
    d = xa.x - ca.x; a0  = d * d;
    d = xa.y - ca.y; a0 += d * d;
    d = xa.z - ca.z; a0 += d * d;
    d = xa.w - ca.w; a0 += d * d;
    d = xb.x - cb.x; a1  = d * d;
    d = xb.y - cb.y; a1 += d * d;
    d = xb.z - cb.z; a1 += d * d;
    d = xb.w - cb.w; a1 += d * d;

    // Reduce within each 16-lane half (4 steps), both slots interleaved.
    #pragma unroll
    for (int o = 8; o > 0; o >>= 1) {
        a0 += __shfl_xor_sync(0xffffffffu, a0, o);
        a1 += __shfl_xor_sync(0xffffffffu, a1, o);
    }
    // On lane 0 after this: a0/a1 = rows row0+0 / row0+2; b0/b1 = rows +1 / +3.
    const float b0 = __shfl_xor_sync(0xffffffffu, a0, 16);
    const float b1 = __shfl_xor_sync(0xffffffffu, a1, 16);

    __shared__ float ws[WARPS_PER_BLOCK];
    if (lane == 0) {
        // clamp per ROW (clip-then-sum), fixed order rows 0,1,2,3.
        float s = fminf(fmaxf(a0, CLAMP_MIN_F), CLAMP_MAX_F);
        s      += fminf(fmaxf(b0, CLAMP_MIN_F), CLAMP_MAX_F);
        s      += fminf(fmaxf(a1, CLAMP_MIN_F), CLAMP_MAX_F);
        s      += fminf(fmaxf(b1, CLAMP_MIN_F), CLAMP_MAX_F);
        ws[warp] = s;
    }
    __syncthreads();

    if (threadIdx.x == 0) {
        float v = 0.0f;
        #pragma unroll
        for (int w = 0; w < WARPS_PER_BLOCK; w++) v += ws[w];
        // No-return float atomic -> REDG (~0.854 cyc/op, 128 ops, one addr).
        atomicAdd(&g_acc, v * (1.0f / (float)BATCH));
        // acq_rel bump: release orders the RED above; acquire for the winner.
        unsigned int t;
        asm volatile("atom.add.acq_rel.gpu.global.u32 %0, [%1], 1;"
                     : "=r"(t) : "l"(&g_arrive_count) : "memory");
        if (t == NUM_BLOCKS - 1) {
            // All 128 REDs happen-before counter==128.
            float total;
            asm volatile("ld.acquire.gpu.global.f32 %0, [%1];"
                         : "=f"(total) : "l"(&g_acc) : "memory");
            // (C-1) masked zeros per row -> CLAMP_MIN each; /B -> (C-1)*MIN.
            const float mask_term = (float)(NUM_CLASSES - 1) * CLAMP_MIN_F;
            out[0] = total + mask_term;
            // Reset for next replay; ordered by the kernel boundary.
            g_acc = 0.0f;
            g_arrive_count = 0;
        }
    }
}

extern "C" void kernel_launch(void* const* d_in, const int* in_sizes, int n_in,
                              void* d_out, int out_size) {
    const float* x       = (const float*)d_in[0];
    const float* centers = (const float*)d_in[1];
    const int*   labels  = (const int*)d_in[2];
    float* out = (float*)d_out;

    center_loss_fused<<<NUM_BLOCKS, BLOCK_THREADS>>>(x, centers, labels, out);
}